// round 10
// baseline (speedup 1.0000x reference)
#include <cuda_runtime.h>
#include <cuda_fp16.h>
#include <stdint.h>

#define BB  4
#define SS  2048
#define DD  1024
#define HH  16
#define DKK 64
#define MM  (BB*SS)   // 8192

// ---------------- scratch (device globals; allocation-free) ----------------
__device__ __align__(16) __half g_hq[MM*DD];
__device__ __align__(16) __half g_hk[MM*DD];
__device__ __align__(16) __half g_hv[MM*DD];
__device__ __align__(16) __half g_wq[DD*DD];
__device__ __align__(16) __half g_wk[DD*DD];
__device__ __align__(16) __half g_wv[DD*DD];
__device__ __align__(16) __half g_wo[DD*DD];
__device__ __align__(16) __half g_qh[MM*DD];   // [B,H,S,DK] fp16
__device__ __align__(16) __half g_kh[MM*DD];
__device__ __align__(16) __half g_vh[MM*DD];
__device__ __align__(16) __half g_av[MM*DD];   // attention output, [B,S,D] fp16

#define CONV_BLOCKS 2048
__device__ int g_viol_b[CONV_BLOCKS];
__device__ int g_sawone_b[CONV_BLOCKS];
__device__ int g_allone_b[CONV_BLOCKS];
__device__ int g_mask_mode;    // 1=i32, 2=u8, 3=f32, 4=f16, 5=bf16
__device__ int g_mask_alltrue;

#define V_I32  1
#define V_U8   2
#define V_F32  4
#define V_F16  8
#define V_BF16 16

// ---------------- helpers ----------------
__device__ __forceinline__ uint32_t smem_u32(const void* p){
    return (uint32_t)__cvta_generic_to_shared(p);
}
__device__ __forceinline__ void cp16(void* s, const void* g){
    asm volatile("cp.async.cg.shared.global [%0], [%1], 16;\n"
        :: "r"(smem_u32(s)), "l"(g));
}
__device__ __forceinline__ void ldsm4(uint32_t& r0, uint32_t& r1, uint32_t& r2, uint32_t& r3, uint32_t a){
    asm volatile("ldmatrix.sync.aligned.m8n8.x4.shared.b16 {%0,%1,%2,%3}, [%4];\n"
        : "=r"(r0),"=r"(r1),"=r"(r2),"=r"(r3) : "r"(a));
}
__device__ __forceinline__ void ldsm4t(uint32_t& r0, uint32_t& r1, uint32_t& r2, uint32_t& r3, uint32_t a){
    asm volatile("ldmatrix.sync.aligned.m8n8.x4.trans.shared.b16 {%0,%1,%2,%3}, [%4];\n"
        : "=r"(r0),"=r"(r1),"=r"(r2),"=r"(r3) : "r"(a));
}
__device__ __forceinline__ void mma16816(float* c,
        uint32_t a0, uint32_t a1, uint32_t a2, uint32_t a3, uint32_t b0, uint32_t b1){
    asm volatile("mma.sync.aligned.m16n8k16.row.col.f32.f16.f16.f32 "
        "{%0,%1,%2,%3}, {%4,%5,%6,%7}, {%8,%9}, {%0,%1,%2,%3};\n"
        : "+f"(c[0]),"+f"(c[1]),"+f"(c[2]),"+f"(c[3])
        : "r"(a0),"r"(a1),"r"(a2),"r"(a3),"r"(b0),"r"(b1));
}
__device__ __forceinline__ float ex2f(float x){
    float y; asm("ex2.approx.f32 %0, %1;" : "=f"(y) : "f"(x)); return y;
}
__device__ __forceinline__ uint32_t packh2(float a, float b){
    __half2 h = __floats2half2_rn(a, b);
    return *reinterpret_cast<uint32_t*>(&h);
}

// ---------------- fused conversion + mask classification ----------------
#define NQ4 (MM*DD/4)
#define NW4 (DD*DD/4)
#define MWORDS (BB*SS*SS/4)

__global__ void conv_classify(const float4* __restrict__ q, const float4* __restrict__ k,
                              const float4* __restrict__ v, const float4* __restrict__ wq,
                              const float4* __restrict__ wk, const float4* __restrict__ wv,
                              const float4* __restrict__ wo, const uint32_t* __restrict__ mk){
    long long total = 3LL*NQ4 + 4LL*NW4;
    long long stride = (long long)gridDim.x * blockDim.x;
    for (long long i = (long long)blockIdx.x*blockDim.x + threadIdx.x; i < total; i += stride){
        const float4* src; __half2* dst; long long j;
        if (i < NQ4){ src = q; dst = (__half2*)g_hq; j = i; }
        else if (i < 2LL*NQ4){ src = k; dst = (__half2*)g_hk; j = i - NQ4; }
        else if (i < 3LL*NQ4){ src = v; dst = (__half2*)g_hv; j = i - 2LL*NQ4; }
        else {
            long long t = i - 3LL*NQ4;
            int ws = (int)(t >> 18);
            j = t & (NW4 - 1);
            src = (ws==0) ? wq : (ws==1) ? wk : (ws==2) ? wv : wo;
            dst = (__half2*)((ws==0) ? g_wq : (ws==1) ? g_wk : (ws==2) ? g_wv : g_wo);
        }
        float4 x = src[j];
        dst[2*j]   = __floats2half2_rn(x.x, x.y);
        dst[2*j+1] = __floats2half2_rn(x.z, x.w);
    }

    int viol = 0, sawone = 0, allone = 1;
    int istride = gridDim.x * blockDim.x;
    for (int i = blockIdx.x*blockDim.x + threadIdx.x; i < MWORDS; i += istride){
        uint32_t w = mk[i];
        if (w == 1u) sawone = 1;
        if (w != 0x01010101u) allone = 0;
        if (!(w == 0u || w == 1u)) viol |= V_I32;
        if ((w & ~0x01010101u) != 0u) viol |= V_U8;
        if (!(w == 0u || w == 0x3F800000u)) viol |= V_F32;
        { uint32_t h0 = w & 0xFFFFu, h1 = w >> 16;
          if (!((h0==0u||h0==0x3C00u) && (h1==0u||h1==0x3C00u))) viol |= V_F16;
          if (!((h0==0u||h0==0x3F80u) && (h1==0u||h1==0x3F80u))) viol |= V_BF16; }
    }
    __shared__ int sv, so, sa;
    if (threadIdx.x == 0){ sv = 0; so = 0; sa = 1; }
    __syncthreads();
    if (viol)    atomicOr(&sv, viol);
    if (sawone)  atomicOr(&so, 1);
    if (!allone) atomicAnd(&sa, 0);
    __syncthreads();
    if (threadIdx.x == 0){
        g_viol_b[blockIdx.x]   = sv;
        g_sawone_b[blockIdx.x] = so;
        g_allone_b[blockIdx.x] = sa;
    }
}

__global__ void mask_finalize(){
    __shared__ int sv, so, sa;
    if (threadIdx.x == 0){ sv = 0; so = 0; sa = 1; }
    __syncthreads();
    int viol = 0, sawone = 0, allone = 1;
    for (int i = threadIdx.x; i < CONV_BLOCKS; i += blockDim.x){
        viol   |= g_viol_b[i];
        sawone |= g_sawone_b[i];
        allone &= g_allone_b[i];
    }
    if (viol)    atomicOr(&sv, viol);
    if (sawone)  atomicOr(&so, 1);
    if (!allone) atomicAnd(&sa, 0);
    __syncthreads();
    if (threadIdx.x == 0){
        int v = sv;
        int mode;
        if      (!(v & V_I32) && so)  mode = 1;
        else if (!(v & V_U8))         mode = 2;
        else if (!(v & V_F32))        mode = 3;
        else if (!(v & V_F16))        mode = 4;
        else if (!(v & V_BF16))       mode = 5;
        else                          mode = 2;
        g_mask_mode = mode;
        g_mask_alltrue = (mode == 2) ? sa : 1;
    }
}

__global__ void mask_cond_scan(const void* __restrict__ m, int nelem){
    int mode = g_mask_mode;
    if (mode == 2) return;
    int stride = gridDim.x * blockDim.x;
    bool anyfalse = false;
    int tid0 = blockIdx.x*blockDim.x + threadIdx.x;
    if (mode == 1){
        const int* p = (const int*)m;
        for (int i = tid0; i < nelem; i += stride) if (p[i] == 0) anyfalse = true;
    } else if (mode == 3){
        const float* p = (const float*)m;
        for (int i = tid0; i < nelem; i += stride) if (p[i] == 0.f) anyfalse = true;
    } else {
        const uint16_t* p = (const uint16_t*)m;
        for (int i = tid0; i < nelem; i += stride) if (p[i] == 0) anyfalse = true;
    }
    if (anyfalse) g_mask_alltrue = 0;
}

__device__ __forceinline__ bool mask_true(const void* m, int mode, size_t idx){
    if (mode == 1) return ((const int*)m)[idx] != 0;
    if (mode == 3) return ((const float*)m)[idx] != 0.f;
    if (mode == 4 || mode == 5) return ((const uint16_t*)m)[idx] != 0;
    return ((const uint8_t*)m)[idx] != 0;
}

// ---------------- HMMA GEMM: 128x128 CTA tile, 32x64 warp tile ----------------
// C[M,N] = A[M,K] * B[N,K]^T.  8 warps: wm=warp>>1 (rows), wn=warp&1 (cols).
template<int JOB>
__device__ __forceinline__ void gemm_body(const __half* __restrict__ A,
                                          const __half* __restrict__ Bw,
                                          __half* __restrict__ outH,
                                          float* __restrict__ outF,
                                          int m0, int n0){
    __shared__ __half As[2][128][40];
    __shared__ __half Bs[2][128][40];

    int tid = threadIdx.x, lane = tid & 31, warp = tid >> 5;
    int wm = warp >> 1, wn = warp & 1;

    float acc[2][8][4];
    #pragma unroll
    for (int i=0;i<2;i++)
        #pragma unroll
        for (int j=0;j<8;j++)
            #pragma unroll
            for (int k2=0;k2<4;k2++) acc[i][j][k2] = 0.f;

    auto load_stage = [&](int kt, int buf){
        int kk = kt * 32;
        #pragma unroll
        for (int i=0;i<2;i++){
            int id = tid + i*256;
            int r = id >> 2, c = (id & 3) << 3;
            cp16(&As[buf][r][c], A  + (size_t)(m0 + r)*DD + kk + c);
            cp16(&Bs[buf][r][c], Bw + (size_t)(n0 + r)*DD + kk + c);
        }
    };

    load_stage(0, 0);
    asm volatile("cp.async.commit_group;\n");

    for (int kt = 0; kt < 32; kt++){
        asm volatile("cp.async.wait_group 0;\n");
        __syncthreads();
        if (kt < 31){
            load_stage(kt+1, (kt+1)&1);
            asm volatile("cp.async.commit_group;\n");
        }
        int buf = kt & 1;
        #pragma unroll
        for (int ks = 0; ks < 2; ks++){
            uint32_t a[2][4];
            #pragma unroll
            for (int mt=0; mt<2; mt++){
                int ar = wm*32 + mt*16 + (lane & 15);
                int ac = ks*16 + ((lane >> 4) << 3);
                ldsm4(a[mt][0],a[mt][1],a[mt][2],a[mt][3], smem_u32(&As[buf][ar][ac]));
            }
            uint32_t bf[4][4];
            #pragma unroll
            for (int p=0;p<4;p++){
                int br = wn*64 + p*16 + ((lane>>4)<<3) + (lane & 7);
                int bc = ks*16 + (((lane>>3)&1)<<3);
                ldsm4(bf[p][0],bf[p][1],bf[p][2],bf[p][3], smem_u32(&Bs[buf][br][bc]));
            }
            #pragma unroll
            for (int mt=0;mt<2;mt++)
                #pragma unroll
                for (int nt=0;nt<8;nt++){
                    uint32_t b0 = bf[nt>>1][(nt&1)?2:0];
                    uint32_t b1 = bf[nt>>1][(nt&1)?3:1];
                    mma16816(acc[mt][nt], a[mt][0],a[mt][1],a[mt][2],a[mt][3], b0, b1);
                }
        }
    }

    int g = lane >> 2, q2 = (lane & 3) << 1;
    #pragma unroll
    for (int mt=0;mt<2;mt++){
        #pragma unroll
        for (int nt=0;nt<8;nt++){
            int row = m0 + wm*32 + mt*16 + g;
            int col = n0 + wn*64 + nt*8 + q2;
            if (JOB == 3){
                *(float2*)(outF + (size_t)row*DD + col)     = make_float2(acc[mt][nt][0], acc[mt][nt][1]);
                *(float2*)(outF + (size_t)(row+8)*DD + col) = make_float2(acc[mt][nt][2], acc[mt][nt][3]);
            } else {
                int b = row >> 11, s = row & 2047;
                int h = col >> 6,  dk = col & 63;
                *(__half2*)(outH + ((size_t)((b*HH + h)*SS + s))*DKK + dk)
                    = __floats2half2_rn(acc[mt][nt][0], acc[mt][nt][1]);
                *(__half2*)(outH + ((size_t)((b*HH + h)*SS + s + 8))*DKK + dk)
                    = __floats2half2_rn(acc[mt][nt][2], acc[mt][nt][3]);
            }
        }
    }
}

__launch_bounds__(256)
__global__ void gemm_qkv(){
    int z = blockIdx.z;
    const __half* A  = (z==0) ? g_hq : (z==1) ? g_hk : g_hv;
    const __half* Bw = (z==0) ? g_wq : (z==1) ? g_wk : g_wv;
    __half* outH     = (z==0) ? g_qh : (z==1) ? g_kh : g_vh;
    gemm_body<0>(A, Bw, outH, nullptr, blockIdx.y*128, blockIdx.x*128);
}

__launch_bounds__(256)
__global__ void gemm_out(float* __restrict__ out){
    gemm_body<3>(g_av, g_wo, nullptr, out, blockIdx.y*128, blockIdx.x*128);
}

// ---------------- flash attention: cp.async double-buffered K/V ----------------
#define FA_SMEM 55296
__launch_bounds__(256)
__global__ void flash_attn(const void* __restrict__ mask){
    extern __shared__ __align__(16) char fsm[];
    __half* Qs = (__half*)fsm;                       // [128][72]
    __half* Ks = (__half*)(fsm + 18432);             // [2][64][72]
    __half* Vs = (__half*)(fsm + 36864);             // [2][64][72]

    int tid = threadIdx.x, lane = tid & 31, w = tid >> 5;
    int qt = blockIdx.x & 15;
    int bh = blockIdx.x >> 4;
    int b  = bh >> 4, h = bh & 15;
    const __half* Qg = g_qh + (size_t)bh*SS*DKK + (size_t)qt*128*DKK;
    const __half* Kg = g_kh + (size_t)bh*SS*DKK;
    const __half* Vg = g_vh + (size_t)bh*SS*DKK;
    const bool maskall = (g_mask_alltrue != 0);
    const int mmode = g_mask_mode;
    const float SCALE = 0.125f;
    const float L2E = 1.4426950408889634f;

    auto kvload = [&](int kt, int bufi){
        const __half* Kt = Kg + (size_t)kt*64*DKK;
        const __half* Vt = Vg + (size_t)kt*64*DKK;
        #pragma unroll
        for (int i=0;i<4;i++){
            int id = tid + i*256;
            if (id < 512){
                int r = id >> 3, c = (id & 7) << 3;
                cp16(Ks + (size_t)bufi*4608 + r*72 + c, Kt + (size_t)r*DKK + c);
            } else {
                int id2 = id - 512;
                int r = id2 >> 3, c = (id2 & 7) << 3;
                cp16(Vs + (size_t)bufi*4608 + r*72 + c, Vt + (size_t)r*DKK + c);
            }
        }
    };

    #pragma unroll
    for (int i=0;i<4;i++){
        int id = tid + i*256;
        int r = id >> 3, c = (id & 7) << 3;
        cp16(Qs + r*72 + c, Qg + (size_t)r*DKK + c);
    }
    kvload(0, 0);
    asm volatile("cp.async.commit_group;\n");
    asm volatile("cp.async.wait_group 0;\n");
    __syncthreads();

    uint32_t qf[4][4];
    #pragma unroll
    for (int ks=0;ks<4;ks++){
        int ar = w*16 + (lane & 15);
        int ac = ks*16 + ((lane >> 4) << 3);
        ldsm4(qf[ks][0],qf[ks][1],qf[ks][2],qf[ks][3], smem_u32(Qs + ar*72 + ac));
    }

    float o[8][4];
    #pragma unroll
    for (int i=0;i<8;i++)
        #pragma unroll
        for (int j=0;j<4;j++) o[i][j] = 0.f;
    float m0v = -1e30f, m1v = -1e30f, l0 = 0.f, l1 = 0.f;
    int g = lane >> 2, q2 = (lane & 3) << 1;

    for (int kt = 0; kt < 32; kt++){
        if (kt > 0){
            asm volatile("cp.async.wait_group 0;\n");
            __syncthreads();
        }
        if (kt < 31){
            kvload(kt+1, (kt+1)&1);
            asm volatile("cp.async.commit_group;\n");
        }
        const __half* Kb = Ks + (size_t)(kt&1)*4608;
        const __half* Vb = Vs + (size_t)(kt&1)*4608;

        float sc[8][4];
        #pragma unroll
        for (int i=0;i<8;i++)
            #pragma unroll
            for (int j=0;j<4;j++) sc[i][j] = 0.f;
        #pragma unroll
        for (int ks=0;ks<4;ks++){
            uint32_t bf[4][4];
            #pragma unroll
            for (int p=0;p<4;p++){
                int br = p*16 + ((lane>>4)<<3) + (lane & 7);
                int bc = ks*16 + (((lane>>3)&1)<<3);
                ldsm4(bf[p][0],bf[p][1],bf[p][2],bf[p][3], smem_u32(Kb + br*72 + bc));
            }
            #pragma unroll
            for (int nt=0;nt<8;nt++){
                uint32_t b0 = bf[nt>>1][(nt&1)?2:0];
                uint32_t b1 = bf[nt>>1][(nt&1)?3:1];
                mma16816(sc[nt], qf[ks][0],qf[ks][1],qf[ks][2],qf[ks][3], b0, b1);
            }
        }

        #pragma unroll
        for (int nt=0;nt<8;nt++)
            #pragma unroll
            for (int j=0;j<4;j++) sc[nt][j] *= SCALE;
        if (!maskall){
            size_t mb = (size_t)b*SS*SS;
            int r0 = qt*128 + w*16 + g;
            #pragma unroll
            for (int nt=0;nt<8;nt++){
                int c0 = kt*64 + nt*8 + q2;
                if (!mask_true(mask, mmode, mb + (size_t)r0*SS + c0))       sc[nt][0] = -1e9f;
                if (!mask_true(mask, mmode, mb + (size_t)r0*SS + c0 + 1))   sc[nt][1] = -1e9f;
                if (!mask_true(mask, mmode, mb + (size_t)(r0+8)*SS + c0))   sc[nt][2] = -1e9f;
                if (!mask_true(mask, mmode, mb + (size_t)(r0+8)*SS + c0+1)) sc[nt][3] = -1e9f;
            }
        }

        float rm0 = -1e30f, rm1 = -1e30f;
        #pragma unroll
        for (int nt=0;nt<8;nt++){
            rm0 = fmaxf(rm0, fmaxf(sc[nt][0], sc[nt][1]));
            rm1 = fmaxf(rm1, fmaxf(sc[nt][2], sc[nt][3]));
        }
        rm0 = fmaxf(rm0, __shfl_xor_sync(0xffffffffu, rm0, 1));
        rm0 = fmaxf(rm0, __shfl_xor_sync(0xffffffffu, rm0, 2));
        rm1 = fmaxf(rm1, __shfl_xor_sync(0xffffffffu, rm1, 1));
        rm1 = fmaxf(rm1, __shfl_xor_sync(0xffffffffu, rm1, 2));
        float mn0 = fmaxf(m0v, rm0), mn1 = fmaxf(m1v, rm1);
        float cr0 = ex2f((m0v - mn0)*L2E), cr1 = ex2f((m1v - mn1)*L2E);
        m0v = mn0; m1v = mn1;

        float rs0 = 0.f, rs1 = 0.f;
        uint32_t pa[4][4];
        #pragma unroll
        for (int ks=0;ks<4;ks++){
            float p00 = ex2f((sc[2*ks  ][0]-mn0)*L2E), p01 = ex2f((sc[2*ks  ][1]-mn0)*L2E);
            float p10 = ex2f((sc[2*ks  ][2]-mn1)*L2E), p11 = ex2f((sc[2*ks  ][3]-mn1)*L2E);
            float p20 = ex2f((sc[2*ks+1][0]-mn0)*L2E), p21 = ex2f((sc[2*ks+1][1]-mn0)*L2E);
            float p30 = ex2f((sc[2*ks+1][2]-mn1)*L2E), p31 = ex2f((sc[2*ks+1][3]-mn1)*L2E);
            rs0 += p00+p01+p20+p21;
            rs1 += p10+p11+p30+p31;
            pa[ks][0] = packh2(p00,p01);
            pa[ks][1] = packh2(p10,p11);
            pa[ks][2] = packh2(p20,p21);
            pa[ks][3] = packh2(p30,p31);
        }
        rs0 += __shfl_xor_sync(0xffffffffu, rs0, 1);
        rs0 += __shfl_xor_sync(0xffffffffu, rs0, 2);
        rs1 += __shfl_xor_sync(0xffffffffu, rs1, 1);
        rs1 += __shfl_xor_sync(0xffffffffu, rs1, 2);
        l0 = l0*cr0 + rs0;
        l1 = l1*cr1 + rs1;
        #pragma unroll
        for (int nt=0;nt<8;nt++){
            o[nt][0] *= cr0; o[nt][1] *= cr0;
            o[nt][2] *= cr1; o[nt][3] *= cr1;
        }

        #pragma unroll
        for (int p=0;p<4;p++){
            #pragma unroll
            for (int ks=0;ks<4;ks++){
                int vr = ks*16 + (lane & 15);
                int vc = p*16 + ((lane >> 4) << 3);
                uint32_t v0,v1,v2,v3;
                ldsm4t(v0,v1,v2,v3, smem_u32(Vb + vr*72 + vc));
                mma16816(o[2*p],   pa[ks][0],pa[ks][1],pa[ks][2],pa[ks][3], v0, v1);
                mma16816(o[2*p+1], pa[ks][0],pa[ks][1],pa[ks][2],pa[ks][3], v2, v3);
            }
        }
    }

    float i0 = 1.f/l0, i1 = 1.f/l1;
    int row = qt*128 + w*16 + g;
    size_t ob0 = ((size_t)b*SS + row    )*DD + h*DKK;
    size_t ob1 = ((size_t)b*SS + row + 8)*DD + h*DKK;
    #pragma unroll
    for (int nt=0;nt<8;nt++){
        *(__half2*)(g_av + ob0 + nt*8 + q2) = __floats2half2_rn(o[nt][0]*i0, o[nt][1]*i0);
        *(__half2*)(g_av + ob1 + nt*8 + q2) = __floats2half2_rn(o[nt][2]*i1, o[nt][3]*i1);
    }
}

// ---------------- launcher ----------------
extern "C" void kernel_launch(void* const* d_in, const int* in_sizes, int n_in,
                              void* d_out, int out_size){
    const float* q    = (const float*)d_in[0];
    const float* k    = (const float*)d_in[1];
    const float* v    = (const float*)d_in[2];
    const void*  mk   = d_in[3];
    const float* w_q  = (const float*)d_in[4];
    const float* w_k  = (const float*)d_in[5];
    const float* w_v  = (const float*)d_in[6];
    const float* w_o  = (const float*)d_in[7];
    float* out = (float*)d_out;

    cudaFuncSetAttribute(flash_attn, cudaFuncAttributeMaxDynamicSharedMemorySize, FA_SMEM);

    const int melems = BB*SS*SS;

    conv_classify<<<CONV_BLOCKS, 256>>>((const float4*)q, (const float4*)k, (const float4*)v,
                                        (const float4*)w_q, (const float4*)w_k,
                                        (const float4*)w_v, (const float4*)w_o,
                                        (const uint32_t*)mk);
    mask_finalize<<<1, 256>>>();
    mask_cond_scan<<<1024, 256>>>(mk, melems);

    dim3 gq(DD/128, MM/128, 3);    // (8, 64, 3) = 1536 CTAs
    gemm_qkv<<<gq, 256>>>();

    flash_attn<<<BB*HH*(SS/128), 256, FA_SMEM>>>(mk);

    dim3 go(DD/128, MM/128);       // (8, 64)
    gemm_out<<<go, 256>>>(out);
}

// round 13
// speedup vs baseline: 1.0037x; 1.0037x over previous
#include <cuda_runtime.h>
#include <cuda_fp16.h>
#include <stdint.h>

#define BB  4
#define SS  2048
#define DD  1024
#define HH  16
#define DKK 64
#define MM  (BB*SS)   // 8192

// ---------------- scratch (device globals; allocation-free) ----------------
__device__ __align__(16) __half g_hq[MM*DD];
__device__ __align__(16) __half g_hk[MM*DD];
__device__ __align__(16) __half g_hv[MM*DD];
__device__ __align__(16) __half g_wq[DD*DD];
__device__ __align__(16) __half g_wk[DD*DD];
__device__ __align__(16) __half g_wv[DD*DD];
__device__ __align__(16) __half g_wo[DD*DD];
__device__ __align__(16) __half g_qh[MM*DD];   // [B,H,S,DK] fp16
__device__ __align__(16) __half g_kh[MM*DD];
__device__ __align__(16) __half g_vh[MM*DD];
__device__ __align__(16) __half g_av[MM*DD];   // attention output, [B,S,D] fp16

#define CONV_BLOCKS 2048
__device__ int g_viol_b[CONV_BLOCKS];
__device__ int g_sawone_b[CONV_BLOCKS];
__device__ int g_allone_b[CONV_BLOCKS];
__device__ int g_mask_mode;    // 1=i32, 2=u8, 3=f32, 4=f16, 5=bf16
__device__ int g_mask_alltrue;

#define V_I32  1
#define V_U8   2
#define V_F32  4
#define V_F16  8
#define V_BF16 16

// ---------------- helpers ----------------
__device__ __forceinline__ uint32_t smem_u32(const void* p){
    return (uint32_t)__cvta_generic_to_shared(p);
}
__device__ __forceinline__ void cp16(void* s, const void* g){
    asm volatile("cp.async.cg.shared.global [%0], [%1], 16;\n"
        :: "r"(smem_u32(s)), "l"(g));
}
__device__ __forceinline__ void ldsm4(uint32_t& r0, uint32_t& r1, uint32_t& r2, uint32_t& r3, uint32_t a){
    asm volatile("ldmatrix.sync.aligned.m8n8.x4.shared.b16 {%0,%1,%2,%3}, [%4];\n"
        : "=r"(r0),"=r"(r1),"=r"(r2),"=r"(r3) : "r"(a));
}
__device__ __forceinline__ void ldsm4t(uint32_t& r0, uint32_t& r1, uint32_t& r2, uint32_t& r3, uint32_t a){
    asm volatile("ldmatrix.sync.aligned.m8n8.x4.trans.shared.b16 {%0,%1,%2,%3}, [%4];\n"
        : "=r"(r0),"=r"(r1),"=r"(r2),"=r"(r3) : "r"(a));
}
__device__ __forceinline__ void mma16816(float* c,
        uint32_t a0, uint32_t a1, uint32_t a2, uint32_t a3, uint32_t b0, uint32_t b1){
    asm volatile("mma.sync.aligned.m16n8k16.row.col.f32.f16.f16.f32 "
        "{%0,%1,%2,%3}, {%4,%5,%6,%7}, {%8,%9}, {%0,%1,%2,%3};\n"
        : "+f"(c[0]),"+f"(c[1]),"+f"(c[2]),"+f"(c[3])
        : "r"(a0),"r"(a1),"r"(a2),"r"(a3),"r"(b0),"r"(b1));
}
__device__ __forceinline__ float ex2f(float x){
    float y; asm("ex2.approx.f32 %0, %1;" : "=f"(y) : "f"(x)); return y;
}
__device__ __forceinline__ uint32_t packh2(float a, float b){
    __half2 h = __floats2half2_rn(a, b);
    return *reinterpret_cast<uint32_t*>(&h);
}

// ---------------- fused conversion + mask classification ----------------
#define NQ4 (MM*DD/4)
#define NW4 (DD*DD/4)
#define MWORDS (BB*SS*SS/4)

__global__ void conv_classify(const float4* __restrict__ q, const float4* __restrict__ k,
                              const float4* __restrict__ v, const float4* __restrict__ wq,
                              const float4* __restrict__ wk, const float4* __restrict__ wv,
                              const float4* __restrict__ wo, const uint32_t* __restrict__ mk){
    long long total = 3LL*NQ4 + 4LL*NW4;
    long long stride = (long long)gridDim.x * blockDim.x;
    for (long long i = (long long)blockIdx.x*blockDim.x + threadIdx.x; i < total; i += stride){
        const float4* src; __half2* dst; long long j;
        if (i < NQ4){ src = q; dst = (__half2*)g_hq; j = i; }
        else if (i < 2LL*NQ4){ src = k; dst = (__half2*)g_hk; j = i - NQ4; }
        else if (i < 3LL*NQ4){ src = v; dst = (__half2*)g_hv; j = i - 2LL*NQ4; }
        else {
            long long t = i - 3LL*NQ4;
            int ws = (int)(t >> 18);
            j = t & (NW4 - 1);
            src = (ws==0) ? wq : (ws==1) ? wk : (ws==2) ? wv : wo;
            dst = (__half2*)((ws==0) ? g_wq : (ws==1) ? g_wk : (ws==2) ? g_wv : g_wo);
        }
        float4 x = src[j];
        dst[2*j]   = __floats2half2_rn(x.x, x.y);
        dst[2*j+1] = __floats2half2_rn(x.z, x.w);
    }

    int viol = 0, sawone = 0, allone = 1;
    int istride = gridDim.x * blockDim.x;
    for (int i = blockIdx.x*blockDim.x + threadIdx.x; i < MWORDS; i += istride){
        uint32_t w = mk[i];
        if (w == 1u) sawone = 1;
        if (w != 0x01010101u) allone = 0;
        if (!(w == 0u || w == 1u)) viol |= V_I32;
        if ((w & ~0x01010101u) != 0u) viol |= V_U8;
        if (!(w == 0u || w == 0x3F800000u)) viol |= V_F32;
        { uint32_t h0 = w & 0xFFFFu, h1 = w >> 16;
          if (!((h0==0u||h0==0x3C00u) && (h1==0u||h1==0x3C00u))) viol |= V_F16;
          if (!((h0==0u||h0==0x3F80u) && (h1==0u||h1==0x3F80u))) viol |= V_BF16; }
    }
    __shared__ int sv, so, sa;
    if (threadIdx.x == 0){ sv = 0; so = 0; sa = 1; }
    __syncthreads();
    if (viol)    atomicOr(&sv, viol);
    if (sawone)  atomicOr(&so, 1);
    if (!allone) atomicAnd(&sa, 0);
    __syncthreads();
    if (threadIdx.x == 0){
        g_viol_b[blockIdx.x]   = sv;
        g_sawone_b[blockIdx.x] = so;
        g_allone_b[blockIdx.x] = sa;
    }
}

__global__ void mask_finalize(){
    __shared__ int sv, so, sa;
    if (threadIdx.x == 0){ sv = 0; so = 0; sa = 1; }
    __syncthreads();
    int viol = 0, sawone = 0, allone = 1;
    for (int i = threadIdx.x; i < CONV_BLOCKS; i += blockDim.x){
        viol   |= g_viol_b[i];
        sawone |= g_sawone_b[i];
        allone &= g_allone_b[i];
    }
    if (viol)    atomicOr(&sv, viol);
    if (sawone)  atomicOr(&so, 1);
    if (!allone) atomicAnd(&sa, 0);
    __syncthreads();
    if (threadIdx.x == 0){
        int v = sv;
        int mode;
        if      (!(v & V_I32) && so)  mode = 1;
        else if (!(v & V_U8))         mode = 2;
        else if (!(v & V_F32))        mode = 3;
        else if (!(v & V_F16))        mode = 4;
        else if (!(v & V_BF16))       mode = 5;
        else                          mode = 2;
        g_mask_mode = mode;
        g_mask_alltrue = (mode == 2) ? sa : 1;
    }
}

__global__ void mask_cond_scan(const void* __restrict__ m, int nelem){
    int mode = g_mask_mode;
    if (mode == 2) return;
    int stride = gridDim.x * blockDim.x;
    bool anyfalse = false;
    int tid0 = blockIdx.x*blockDim.x + threadIdx.x;
    if (mode == 1){
        const int* p = (const int*)m;
        for (int i = tid0; i < nelem; i += stride) if (p[i] == 0) anyfalse = true;
    } else if (mode == 3){
        const float* p = (const float*)m;
        for (int i = tid0; i < nelem; i += stride) if (p[i] == 0.f) anyfalse = true;
    } else {
        const uint16_t* p = (const uint16_t*)m;
        for (int i = tid0; i < nelem; i += stride) if (p[i] == 0) anyfalse = true;
    }
    if (anyfalse) g_mask_alltrue = 0;
}

__device__ __forceinline__ bool mask_true(const void* m, int mode, size_t idx){
    if (mode == 1) return ((const int*)m)[idx] != 0;
    if (mode == 3) return ((const float*)m)[idx] != 0.f;
    if (mode == 4 || mode == 5) return ((const uint16_t*)m)[idx] != 0;
    return ((const uint8_t*)m)[idx] != 0;
}

// ---------------- HMMA GEMM: 128x128 CTA tile, K-chunk 64, dyn smem ----------------
// layout in dynamic smem (halves): As[2][128][72] then Bs[2][128][72]
#define GE_STG   9216               // halves per stage (128*72)
#define GE_SMEM  (4*GE_STG*2)       // 73728 bytes
template<int JOB>
__device__ __forceinline__ void gemm_body(const __half* __restrict__ A,
                                          const __half* __restrict__ Bw,
                                          __half* __restrict__ outH,
                                          float* __restrict__ outF,
                                          int m0, int n0){
    extern __shared__ __align__(16) __half gsm[];
    __half* As = gsm;                 // [2][128][72]
    __half* Bs = gsm + 2*GE_STG;      // [2][128][72]

    int tid = threadIdx.x, lane = tid & 31, warp = tid >> 5;
    int wm = warp >> 1, wn = warp & 1;

    float acc[2][8][4];
    #pragma unroll
    for (int i=0;i<2;i++)
        #pragma unroll
        for (int j=0;j<8;j++)
            #pragma unroll
            for (int k2=0;k2<4;k2++) acc[i][j][k2] = 0.f;

    auto load_stage = [&](int kt, int buf){
        int kk = kt * 64;
        #pragma unroll
        for (int i=0;i<4;i++){
            int id = tid + i*256;       // 1024 blocks of 8 halves per matrix
            int r = id >> 3, c = (id & 7) << 3;
            cp16(As + buf*GE_STG + r*72 + c, A  + (size_t)(m0 + r)*DD + kk + c);
            cp16(Bs + buf*GE_STG + r*72 + c, Bw + (size_t)(n0 + r)*DD + kk + c);
        }
    };

    load_stage(0, 0);
    asm volatile("cp.async.commit_group;\n");

    for (int kt = 0; kt < 16; kt++){
        asm volatile("cp.async.wait_group 0;\n");
        __syncthreads();
        if (kt < 15){
            load_stage(kt+1, (kt+1)&1);
            asm volatile("cp.async.commit_group;\n");
        }
        int buf = kt & 1;
        const __half* Ab = As + buf*GE_STG;
        const __half* Bb = Bs + buf*GE_STG;
        #pragma unroll
        for (int ks = 0; ks < 4; ks++){
            uint32_t a[2][4];
            #pragma unroll
            for (int mt=0; mt<2; mt++){
                int ar = wm*32 + mt*16 + (lane & 15);
                int ac = ks*16 + ((lane >> 4) << 3);
                ldsm4(a[mt][0],a[mt][1],a[mt][2],a[mt][3], smem_u32(Ab + ar*72 + ac));
            }
            uint32_t bf[4][4];
            #pragma unroll
            for (int p=0;p<4;p++){
                int br = wn*64 + p*16 + ((lane>>4)<<3) + (lane & 7);
                int bc = ks*16 + (((lane>>3)&1)<<3);
                ldsm4(bf[p][0],bf[p][1],bf[p][2],bf[p][3], smem_u32(Bb + br*72 + bc));
            }
            #pragma unroll
            for (int mt=0;mt<2;mt++)
                #pragma unroll
                for (int nt=0;nt<8;nt++){
                    uint32_t b0 = bf[nt>>1][(nt&1)?2:0];
                    uint32_t b1 = bf[nt>>1][(nt&1)?3:1];
                    mma16816(acc[mt][nt], a[mt][0],a[mt][1],a[mt][2],a[mt][3], b0, b1);
                }
        }
    }

    int g = lane >> 2, q2 = (lane & 3) << 1;
    #pragma unroll
    for (int mt=0;mt<2;mt++){
        #pragma unroll
        for (int nt=0;nt<8;nt++){
            int row = m0 + wm*32 + mt*16 + g;
            int col = n0 + wn*64 + nt*8 + q2;
            if (JOB == 3){
                *(float2*)(outF + (size_t)row*DD + col)     = make_float2(acc[mt][nt][0], acc[mt][nt][1]);
                *(float2*)(outF + (size_t)(row+8)*DD + col) = make_float2(acc[mt][nt][2], acc[mt][nt][3]);
            } else {
                int b = row >> 11, s = row & 2047;
                int h = col >> 6,  dk = col & 63;
                *(__half2*)(outH + ((size_t)((b*HH + h)*SS + s))*DKK + dk)
                    = __floats2half2_rn(acc[mt][nt][0], acc[mt][nt][1]);
                *(__half2*)(outH + ((size_t)((b*HH + h)*SS + s + 8))*DKK + dk)
                    = __floats2half2_rn(acc[mt][nt][2], acc[mt][nt][3]);
            }
        }
    }
}

__launch_bounds__(256)
__global__ void gemm_qkv(){
    int z = blockIdx.z;
    const __half* A  = (z==0) ? g_hq : (z==1) ? g_hk : g_hv;
    const __half* Bw = (z==0) ? g_wq : (z==1) ? g_wk : g_wv;
    __half* outH     = (z==0) ? g_qh : (z==1) ? g_kh : g_vh;
    gemm_body<0>(A, Bw, outH, nullptr, blockIdx.y*128, blockIdx.x*128);
}

__launch_bounds__(256)
__global__ void gemm_out(float* __restrict__ out){
    gemm_body<3>(g_av, g_wo, nullptr, out, blockIdx.y*128, blockIdx.x*128);
}

// ---------------- flash attention: 128-row K/V per commit, halves of 64 ----------------
// dyn smem: Qs[128][72] @0, Ks[2][128][72] @18432B, Vs[2][128][72] @55296B
#define FA_KSTG 9216                 // halves per K/V stage (128*72)
#define FA_SMEM 92160
__launch_bounds__(256)
__global__ void flash_attn(const void* __restrict__ mask){
    extern __shared__ __align__(16) char fsm[];
    __half* Qs = (__half*)fsm;                     // [128][72]
    __half* Ks = (__half*)(fsm + 18432);           // [2][128][72]
    __half* Vs = (__half*)(fsm + 55296);           // [2][128][72]

    int tid = threadIdx.x, lane = tid & 31, w = tid >> 5;
    int qt = blockIdx.x & 15;
    int bh = blockIdx.x >> 4;
    int b  = bh >> 4, h = bh & 15;
    const __half* Qg = g_qh + (size_t)bh*SS*DKK + (size_t)qt*128*DKK;
    const __half* Kg = g_kh + (size_t)bh*SS*DKK;
    const __half* Vg = g_vh + (size_t)bh*SS*DKK;
    const bool maskall = (g_mask_alltrue != 0);
    const int mmode = g_mask_mode;
    const float SCALE = 0.125f;
    const float L2E = 1.4426950408889634f;

    // load 128 K-rows + 128 V-rows for super-tile t2 into buffer bufi
    auto kvload = [&](int t2, int bufi){
        const __half* Kt = Kg + (size_t)t2*128*DKK;
        const __half* Vt = Vg + (size_t)t2*128*DKK;
        #pragma unroll
        for (int i=0;i<8;i++){
            int id = tid + i*256;       // 2048 blocks: 1024 K + 1024 V
            if (id < 1024){
                int r = id >> 3, c = (id & 7) << 3;
                cp16(Ks + bufi*FA_KSTG + r*72 + c, Kt + (size_t)r*DKK + c);
            } else {
                int id2 = id - 1024;
                int r = id2 >> 3, c = (id2 & 7) << 3;
                cp16(Vs + bufi*FA_KSTG + r*72 + c, Vt + (size_t)r*DKK + c);
            }
        }
    };

    #pragma unroll
    for (int i=0;i<4;i++){
        int id = tid + i*256;
        int r = id >> 3, c = (id & 7) << 3;
        cp16(Qs + r*72 + c, Qg + (size_t)r*DKK + c);
    }
    kvload(0, 0);
    asm volatile("cp.async.commit_group;\n");
    asm volatile("cp.async.wait_group 0;\n");
    __syncthreads();

    uint32_t qf[4][4];
    #pragma unroll
    for (int ks=0;ks<4;ks++){
        int ar = w*16 + (lane & 15);
        int ac = ks*16 + ((lane >> 4) << 3);
        ldsm4(qf[ks][0],qf[ks][1],qf[ks][2],qf[ks][3], smem_u32(Qs + ar*72 + ac));
    }

    float o[8][4];
    #pragma unroll
    for (int i=0;i<8;i++)
        #pragma unroll
        for (int j=0;j<4;j++) o[i][j] = 0.f;
    float m0v = -1e30f, m1v = -1e30f, l0 = 0.f, l1 = 0.f;
    int g = lane >> 2, q2 = (lane & 3) << 1;

    for (int t2 = 0; t2 < 16; t2++){
        if (t2 > 0){
            asm volatile("cp.async.wait_group 0;\n");
            __syncthreads();
        }
        if (t2 < 15){
            kvload(t2+1, (t2+1)&1);
            asm volatile("cp.async.commit_group;\n");
        }
        int buf = t2 & 1;

        #pragma unroll
        for (int hh = 0; hh < 2; hh++){
            const __half* Kb = Ks + buf*FA_KSTG + hh*64*72;
            const __half* Vb = Vs + buf*FA_KSTG + hh*64*72;
            int col0 = t2*128 + hh*64;

            float sc[8][4];
            #pragma unroll
            for (int i=0;i<8;i++)
                #pragma unroll
                for (int j=0;j<4;j++) sc[i][j] = 0.f;
            #pragma unroll
            for (int ks=0;ks<4;ks++){
                uint32_t bf[4][4];
                #pragma unroll
                for (int p=0;p<4;p++){
                    int br = p*16 + ((lane>>4)<<3) + (lane & 7);
                    int bc = ks*16 + (((lane>>3)&1)<<3);
                    ldsm4(bf[p][0],bf[p][1],bf[p][2],bf[p][3], smem_u32(Kb + br*72 + bc));
                }
                #pragma unroll
                for (int nt=0;nt<8;nt++){
                    uint32_t b0 = bf[nt>>1][(nt&1)?2:0];
                    uint32_t b1 = bf[nt>>1][(nt&1)?3:1];
                    mma16816(sc[nt], qf[ks][0],qf[ks][1],qf[ks][2],qf[ks][3], b0, b1);
                }
            }

            #pragma unroll
            for (int nt=0;nt<8;nt++)
                #pragma unroll
                for (int j=0;j<4;j++) sc[nt][j] *= SCALE;
            if (!maskall){
                size_t mb = (size_t)b*SS*SS;
                int r0 = qt*128 + w*16 + g;
                #pragma unroll
                for (int nt=0;nt<8;nt++){
                    int c0 = col0 + nt*8 + q2;
                    if (!mask_true(mask, mmode, mb + (size_t)r0*SS + c0))       sc[nt][0] = -1e9f;
                    if (!mask_true(mask, mmode, mb + (size_t)r0*SS + c0 + 1))   sc[nt][1] = -1e9f;
                    if (!mask_true(mask, mmode, mb + (size_t)(r0+8)*SS + c0))   sc[nt][2] = -1e9f;
                    if (!mask_true(mask, mmode, mb + (size_t)(r0+8)*SS + c0+1)) sc[nt][3] = -1e9f;
                }
            }

            float rm0 = -1e30f, rm1 = -1e30f;
            #pragma unroll
            for (int nt=0;nt<8;nt++){
                rm0 = fmaxf(rm0, fmaxf(sc[nt][0], sc[nt][1]));
                rm1 = fmaxf(rm1, fmaxf(sc[nt][2], sc[nt][3]));
            }
            rm0 = fmaxf(rm0, __shfl_xor_sync(0xffffffffu, rm0, 1));
            rm0 = fmaxf(rm0, __shfl_xor_sync(0xffffffffu, rm0, 2));
            rm1 = fmaxf(rm1, __shfl_xor_sync(0xffffffffu, rm1, 1));
            rm1 = fmaxf(rm1, __shfl_xor_sync(0xffffffffu, rm1, 2));
            float mn0 = fmaxf(m0v, rm0), mn1 = fmaxf(m1v, rm1);
            float cr0 = ex2f((m0v - mn0)*L2E), cr1 = ex2f((m1v - mn1)*L2E);
            m0v = mn0; m1v = mn1;

            float rs0 = 0.f, rs1 = 0.f;
            uint32_t pa[4][4];
            #pragma unroll
            for (int ks=0;ks<4;ks++){
                float p00 = ex2f((sc[2*ks  ][0]-mn0)*L2E), p01 = ex2f((sc[2*ks  ][1]-mn0)*L2E);
                float p10 = ex2f((sc[2*ks  ][2]-mn1)*L2E), p11 = ex2f((sc[2*ks  ][3]-mn1)*L2E);
                float p20 = ex2f((sc[2*ks+1][0]-mn0)*L2E), p21 = ex2f((sc[2*ks+1][1]-mn0)*L2E);
                float p30 = ex2f((sc[2*ks+1][2]-mn1)*L2E), p31 = ex2f((sc[2*ks+1][3]-mn1)*L2E);
                rs0 += p00+p01+p20+p21;
                rs1 += p10+p11+p30+p31;
                pa[ks][0] = packh2(p00,p01);
                pa[ks][1] = packh2(p10,p11);
                pa[ks][2] = packh2(p20,p21);
                pa[ks][3] = packh2(p30,p31);
            }
            rs0 += __shfl_xor_sync(0xffffffffu, rs0, 1);
            rs0 += __shfl_xor_sync(0xffffffffu, rs0, 2);
            rs1 += __shfl_xor_sync(0xffffffffu, rs1, 1);
            rs1 += __shfl_xor_sync(0xffffffffu, rs1, 2);
            l0 = l0*cr0 + rs0;
            l1 = l1*cr1 + rs1;
            #pragma unroll
            for (int nt=0;nt<8;nt++){
                o[nt][0] *= cr0; o[nt][1] *= cr0;
                o[nt][2] *= cr1; o[nt][3] *= cr1;
            }

            #pragma unroll
            for (int p=0;p<4;p++){
                #pragma unroll
                for (int ks=0;ks<4;ks++){
                    int vr = ks*16 + (lane & 15);
                    int vc = p*16 + ((lane >> 4) << 3);
                    uint32_t v0,v1,v2,v3;
                    ldsm4t(v0,v1,v2,v3, smem_u32(Vb + vr*72 + vc));
                    mma16816(o[2*p],   pa[ks][0],pa[ks][1],pa[ks][2],pa[ks][3], v0, v1);
                    mma16816(o[2*p+1], pa[ks][0],pa[ks][1],pa[ks][2],pa[ks][3], v2, v3);
                }
            }
        }
    }

    float i0 = 1.f/l0, i1 = 1.f/l1;
    int row = qt*128 + w*16 + g;
    size_t ob0 = ((size_t)b*SS + row    )*DD + h*DKK;
    size_t ob1 = ((size_t)b*SS + row + 8)*DD + h*DKK;
    #pragma unroll
    for (int nt=0;nt<8;nt++){
        *(__half2*)(g_av + ob0 + nt*8 + q2) = __floats2half2_rn(o[nt][0]*i0, o[nt][1]*i0);
        *(__half2*)(g_av + ob1 + nt*8 + q2) = __floats2half2_rn(o[nt][2]*i1, o[nt][3]*i1);
    }
}

// ---------------- launcher ----------------
extern "C" void kernel_launch(void* const* d_in, const int* in_sizes, int n_in,
                              void* d_out, int out_size){
    const float* q    = (const float*)d_in[0];
    const float* k    = (const float*)d_in[1];
    const float* v    = (const float*)d_in[2];
    const void*  mk   = d_in[3];
    const float* w_q  = (const float*)d_in[4];
    const float* w_k  = (const float*)d_in[5];
    const float* w_v  = (const float*)d_in[6];
    const float* w_o  = (const float*)d_in[7];
    float* out = (float*)d_out;

    cudaFuncSetAttribute(flash_attn, cudaFuncAttributeMaxDynamicSharedMemorySize, FA_SMEM);
    cudaFuncSetAttribute(gemm_qkv,   cudaFuncAttributeMaxDynamicSharedMemorySize, GE_SMEM);
    cudaFuncSetAttribute(gemm_out,   cudaFuncAttributeMaxDynamicSharedMemorySize, GE_SMEM);

    const int melems = BB*SS*SS;

    conv_classify<<<CONV_BLOCKS, 256>>>((const float4*)q, (const float4*)k, (const float4*)v,
                                        (const float4*)w_q, (const float4*)w_k,
                                        (const float4*)w_v, (const float4*)w_o,
                                        (const uint32_t*)mk);
    mask_finalize<<<1, 256>>>();
    mask_cond_scan<<<1024, 256>>>(mk, melems);

    dim3 gq(DD/128, MM/128, 3);    // (8, 64, 3) = 1536 CTAs
    gemm_qkv<<<gq, 256, GE_SMEM>>>();

    flash_attn<<<BB*HH*(SS/128), 256, FA_SMEM>>>(mk);

    dim3 go(DD/128, MM/128);       // (8, 64)
    gemm_out<<<go, 256, GE_SMEM>>>(out);
}